// round 16
// baseline (speedup 1.0000x reference)
#include <cuda_runtime.h>
#include <cuda_fp16.h>
#include <cuda_bf16.h>
#include <math.h>
#include <stdint.h>

// ---------------------------------------------------------------------------
// Problem constants
// ---------------------------------------------------------------------------
#define BB 32      // batch
#define SS 128     // seq len
#define DD 300     // emb dim
#define HH 1024    // hidden
#define G4 4096    // 4*H
#define NT 9       // tags
#define LBLK 128   // persistent LSTM CTAs (single wave, <148 SMs)
#define DBAR 64    // per-direction barrier arrivals

// lstm dynamic smem: Bsm u32[16384] (64KB) + psum float[2*64*33] + hstage 1KB
#define LSTM_SMEM (65536 + 2 * 64 * 33 * 4 + 1024)

// ---------------------------------------------------------------------------
// Scratch (static device allocations - allowed)
// ---------------------------------------------------------------------------
__device__ float g_X1[4096 * 2048];             // fp32 layer-3 output for bn_lin2
__device__ __half g_pre[2ull * 4096 * 4096];    // fp16 input projections
__device__ float g_emis[BB * SS * NT];
// Whh fp16, A-fragment order: [cta 128][kstep 64][mtile 4][lane 32][4 u32]
__device__ uint4 g_Ahi[128 * 8192];
// h as fp16 B-fragments, parity double-buffered: [parity][dir][16384 u32]
__device__ uint32_t g_hfrag[2][2][16384];
// input-projection A-fragments, ping-pong
__device__ uint4 g_Xf[2][64 * 128 * 4 * 32];
// Wih B-fragments (reused per layer)
__device__ uint2 g_Wf[256 * 128 * 4 * 32];
// lin1 weight B-fragments (N=512, KS=19)
__device__ uint2 g_WfL1[16 * 19 * 4 * 32];

__device__ unsigned g_bar_cnt[2];
__device__ unsigned g_bar_gen[2];

// mma.sync m16n8k16 fp16 -> f32 (baseline PTX, compiles for plain sm_103)
#define MMA_F16(d, a, b) \
    asm volatile("mma.sync.aligned.m16n8k16.row.col.f32.f16.f16.f32 " \
        "{%0,%1,%2,%3}, {%4,%5,%6,%7}, {%8,%9}, {%0,%1,%2,%3};" \
        : "+f"((d)[0]), "+f"((d)[1]), "+f"((d)[2]), "+f"((d)[3]) \
        : "r"((a).x), "r"((a).y), "r"((a).z), "r"((a).w), \
          "r"((b).x), "r"((b).y))

__device__ __forceinline__ uint32_t pack_h2(float a, float b) {
    return (uint32_t)__half_as_ushort(__float2half_rn(a)) |
           ((uint32_t)__half_as_ushort(__float2half_rn(b)) << 16);
}

// ---------------------------------------------------------------------------
// Whh fp32 -> fp16 A-fragments, one u32 (k-pair) per thread.
// ---------------------------------------------------------------------------
__global__ void convw_kernel(const float* __restrict__ whh,
                             uint32_t* __restrict__ Ahi) {
    int i = blockIdx.x * blockDim.x + threadIdx.x;   // 128*64*512
    if (i >= 128 * 64 * 512) return;
    int c = i >> 15;
    int r = (i >> 9) & 63;
    int kp = i & 511;
    int kstep = kp >> 3, p = kp & 7;
    int k0 = kstep * 16 + p * 2;
    int dir = c >> 6, j0 = (c & 63) * 16;
    int gate = r >> 4, jj = r & 15;
    int grow = gate * 1024 + j0 + jj;
    const float* wp = whh + (size_t)dir * G4 * HH + (size_t)grow * HH + k0;
    float w0 = wp[0], w1 = wp[1];
    int lane = (jj & 7) * 4 + (p & 3);
    int reg = ((jj >> 3) & 1) + ((p >> 2) << 1);
    size_t idx = (size_t)c * 32768 + kstep * 512 + gate * 128 + lane * 4 + reg;
    Ahi[idx] = pack_h2(w0, w1);
}

// ---------------------------------------------------------------------------
// Wih fp32 (8192 x K) -> fp16 B-fragments, one u32 per thread.
// ---------------------------------------------------------------------------
__global__ void convwih_kernel(const float* __restrict__ W,
                               uint32_t* __restrict__ Wf, int K, int KS) {
    int i = blockIdx.x * blockDim.x + threadIdx.x;   // 8192*(K/2)
    int KH = K >> 1;
    if (i >= 8192 * KH) return;
    int n = i / KH, kp = i % KH;
    int kstep = kp >> 3, p = kp & 7;
    int k0 = kstep * 16 + p * 2;
    const float* wp = W + (size_t)n * K + k0;
    float w0 = wp[0], w1 = wp[1];
    int nblk = n >> 5, nr = n & 31;
    int nt = nr >> 3, ncol = nr & 7;
    int lane = ncol * 4 + (p & 3);
    int reg = p >> 2;
    size_t idx = ((((size_t)nblk * KS + kstep) * 4 + nt) * 32 + lane) * 2 + reg;
    Wf[idx] = pack_h2(w0, w1);
}

// ---------------------------------------------------------------------------
// Embedding gather -> fp16 A-fragments (K=304, KS=19, zero pad 300..303)
// ---------------------------------------------------------------------------
__global__ void convE_kernel(const int* __restrict__ x, const float* __restrict__ emb,
                             __half* __restrict__ Ef) {
    int i = blockIdx.x * blockDim.x + threadIdx.x;   // 4096*304
    if (i >= 4096 * 304) return;
    int m = i / 304, k = i % 304;
    int s = m / BB, b = m % BB;
    int tok = x[b * SS + s];
    float v = (k < DD) ? emb[(size_t)tok * DD + k] : 0.f;
    int rowblk = m >> 6, r = m & 63;
    int mt = r >> 4, mrow = r & 15;
    int kstep = k >> 4, kin = k & 15;
    int lane = (mrow & 7) * 4 + ((kin >> 1) & 3);
    int reg = ((mrow >> 3) & 1) + ((kin >> 3) << 1);
    size_t e = (((((size_t)rowblk * 19 + kstep) * 4 + mt) * 32 + lane) * 4 + reg) * 2
               + (kin & 1);
    Ef[e] = __float2half_rn(v);
}

// lin1 weight (512 x 300) -> B-fragments (N=512, KS=19, zero pad)
__global__ void convW1_kernel(const float* __restrict__ W, __half* __restrict__ Wf) {
    int i = blockIdx.x * blockDim.x + threadIdx.x;   // 512*304
    if (i >= 512 * 304) return;
    int n = i / 304, k = i % 304;
    float v = (k < DD) ? W[(size_t)n * DD + k] : 0.f;
    int nblk = n >> 5, nr = n & 31;
    int nt = nr >> 3, ncol = nr & 7;
    int kstep = k >> 4, kin = k & 15;
    int lane = ncol * 4 + ((kin & 7) >> 1);
    int reg = kin >> 3;
    size_t e = (((((size_t)nblk * 19 + kstep) * 4 + nt) * 32 + lane) * 2 + reg) * 2
               + (kin & 1);
    Wf[e] = __float2half_rn(v);
}

// ---------------------------------------------------------------------------
// HMMA lin1: X0frag[m][n] = E[m] . W1[n] + b1[n], written directly as
// fp16 A-fragments (KS=32) for layer-0 hgemm. Grid (2, 32), 512 threads.
// Prefetch ring depth 2.
// ---------------------------------------------------------------------------
__global__ void __launch_bounds__(512, 1)
hgemm_lin1(const uint4* __restrict__ Ef, const uint2* __restrict__ Wf,
           const float* __restrict__ bias, __half* __restrict__ Xf0) {
    const int tid = threadIdx.x;
    const int wid = tid >> 5, lane = tid & 31;
    const int rowblk = blockIdx.y * 2 + (wid >> 3);
    const int nblk = blockIdx.x * 8 + (wid & 7);

    const uint4* Ab = Ef + (size_t)rowblk * 19 * 128 + lane;
    const uint2* Bb = Wf + (size_t)nblk * 19 * 128 + lane;

    float d[4][4][4];
#pragma unroll
    for (int mt = 0; mt < 4; mt++)
#pragma unroll
        for (int nt = 0; nt < 4; nt++)
#pragma unroll
            for (int q = 0; q < 4; q++) d[mt][nt][q] = 0.f;

    uint4 a[2][4];
    uint2 b[2][4];
#pragma unroll
    for (int i = 0; i < 4; i++) {
        a[0][i] = __ldg(Ab + i * 32);
        b[0][i] = __ldg(Bb + i * 32);
        a[1][i] = __ldg(Ab + 128 + i * 32);
        b[1][i] = __ldg(Bb + 128 + i * 32);
    }
    for (int ks = 0; ks < 19; ks++) {
        int p = ks & 1;
#pragma unroll
        for (int mt = 0; mt < 4; mt++)
#pragma unroll
            for (int nt = 0; nt < 4; nt++)
                MMA_F16(d[mt][nt], a[p][mt], b[p][nt]);
        if (ks + 2 < 19) {
            const uint4* An = Ab + (size_t)(ks + 2) * 128;
            const uint2* Bn = Bb + (size_t)(ks + 2) * 128;
#pragma unroll
            for (int i = 0; i < 4; i++) {
                a[p][i] = __ldg(An + i * 32);
                b[p][i] = __ldg(Bn + i * 32);
            }
        }
    }

    // epilogue: bias + write fp16 A-fragments (KS=32) for layer-0 hgemm
#pragma unroll
    for (int mt = 0; mt < 4; mt++) {
#pragma unroll
        for (int nt = 0; nt < 4; nt++) {
#pragma unroll
            for (int q = 0; q < 4; q++) {
                int n = nblk * 32 + nt * 8 + (lane & 3) * 2 + (q & 1);
                int mm = rowblk * 64 + mt * 16 + (lane >> 2) + ((q >> 1) << 3);
                float val = d[mt][nt][q] + __ldg(bias + n);
                int kstep = n >> 4, kin = n & 15;
                int rb = mm >> 6, r = mm & 63;
                int mtA = r >> 4, mr = r & 15;
                int lane2 = (mr & 7) * 4 + ((kin >> 1) & 3);
                int reg = ((mr >> 3) & 1) + ((kin >> 3) << 1);
                size_t e = (((((size_t)rb * 32 + kstep) * 4 + mtA) * 32 + lane2) * 4
                            + reg) * 2 + (kin & 1);
                Xf0[e] = __float2half_rn(val);
            }
        }
    }
}

// ---------------------------------------------------------------------------
// HMMA input-projection GEMM: pre[dir][m][col] = X[m] . Wih[n] + bias[n]
// Grid (32, 32), 512 threads; fp16 output; prefetch ring depth 2.
// ---------------------------------------------------------------------------
__global__ void __launch_bounds__(512, 1)
hgemm_pre(const uint4* __restrict__ Xf, const uint2* __restrict__ Wf,
          const float* __restrict__ bias, __half* __restrict__ pre, int KS) {
    const int tid = threadIdx.x;
    const int wid = tid >> 5, lane = tid & 31;
    const int rowblk = blockIdx.y * 2 + (wid >> 3);
    const int nblk = blockIdx.x * 8 + (wid & 7);

    const uint4* Ab = Xf + (size_t)rowblk * KS * 128 + lane;
    const uint2* Bb = Wf + (size_t)nblk * KS * 128 + lane;

    float d[4][4][4];
#pragma unroll
    for (int mt = 0; mt < 4; mt++)
#pragma unroll
        for (int nt = 0; nt < 4; nt++)
#pragma unroll
            for (int q = 0; q < 4; q++) d[mt][nt][q] = 0.f;

    uint4 a[2][4];
    uint2 b[2][4];
#pragma unroll
    for (int i = 0; i < 4; i++) {
        a[0][i] = __ldg(Ab + i * 32);
        b[0][i] = __ldg(Bb + i * 32);
        a[1][i] = __ldg(Ab + 128 + i * 32);
        b[1][i] = __ldg(Bb + 128 + i * 32);
    }

    for (int ks = 0; ks < KS; ks++) {
        int p = ks & 1;
#pragma unroll
        for (int mt = 0; mt < 4; mt++)
#pragma unroll
            for (int nt = 0; nt < 4; nt++)
                MMA_F16(d[mt][nt], a[p][mt], b[p][nt]);
        if (ks + 2 < KS) {
            const uint4* An = Ab + (size_t)(ks + 2) * 128;
            const uint2* Bn = Bb + (size_t)(ks + 2) * 128;
#pragma unroll
            for (int i = 0; i < 4; i++) {
                a[p][i] = __ldg(An + i * 32);
                b[p][i] = __ldg(Bn + i * 32);
            }
        }
    }

#pragma unroll
    for (int mt = 0; mt < 4; mt++) {
        int m = rowblk * 64 + mt * 16 + (lane >> 2);
#pragma unroll
        for (int nt = 0; nt < 4; nt++) {
            int nn = nblk * 32 + nt * 8 + (lane & 3) * 2;
            int dir = nn >> 12;
            int col = nn & 4095;
            float bs0 = __ldg(bias + nn);
            float bs1 = __ldg(bias + nn + 1);
            __half2* outp = (__half2*)(pre + (size_t)dir * 4096 * 4096
                                       + (size_t)m * 4096 + col);
            *outp = __floats2half2_rn(d[mt][nt][0] + bs0, d[mt][nt][1] + bs1);
            *(outp + (size_t)8 * 2048) =
                __floats2half2_rn(d[mt][nt][2] + bs0, d[mt][nt][3] + bs1);
        }
    }
}

// ---------------------------------------------------------------------------
// Persistent HMMA BiLSTM layer. 128 CTAs x 512 threads. fp16 pre.
// Split arrive/wait barrier (tight spin); coalesced h-frag publish; shadow work.
// ---------------------------------------------------------------------------
__global__ void __launch_bounds__(512, 1)
lstm_mma(const uint4* __restrict__ Ahi, const __half* __restrict__ pre,
         float* __restrict__ Xout, __half* __restrict__ Xfout) {
    extern __shared__ __align__(16) uint32_t smd[];
    uint32_t* Bsm = smd;                           // u32[16384] = 64 KB
    float* psum = (float*)(smd + 16384);           // [ksplit][64 rows][33]
    __half* hstage = (__half*)(smd + 16384 + 2 * 64 * 33);  // 512 halves

    const int tid = threadIdx.x;
    const int wid = tid >> 5;
    const int lid = tid & 31;
    const int cta = blockIdx.x;
    const int dir = cta >> 6;
    const int my_kstep = cta & 63;
    const int j0 = my_kstep * 16;

    const int ksplit = wid >> 3;
    const int mtile  = (wid >> 1) & 3;
    const int ntbase = (wid & 1) * 2;
    const int kbase  = ksplit * 32;

    const uint4* Aph = Ahi + (size_t)cta * 8192 + (size_t)kbase * 128 + mtile * 32 + lid;
    const __half* preD = pre + (size_t)dir * 4096 * 4096;

    const int cb = tid >> 4;
    const int cj = tid & 15;
    float creg = 0.f;

    const int kx = dir * HH + j0 + cj;
    const int xkstep = kx >> 4, xkin = kx & 15;

    const int hloc = (((cb >> 3) * 32 + (cb & 7) * 4 + ((cj & 7) >> 1)) * 2
                      + (cj >> 3)) * 2 + (cj & 1);

    volatile unsigned* vgen = &g_bar_gen[dir];
    const unsigned base = *vgen;

    float pg0, pg1, pg2, pg3;
    {
        const int sd0 = dir ? (SS - 1) : 0;
        const __half* pp = preD + (size_t)sd0 * BB * G4 + (size_t)cb * G4 + j0 + cj;
        pg0 = __half2float(__ldcg(pp));
        pg1 = __half2float(__ldcg(pp + 1024));
        pg2 = __half2float(__ldcg(pp + 2048));
        pg3 = __half2float(__ldcg(pp + 3072));
    }

    for (int t = 0; t < SS; t++) {
        const int sdir = dir ? (SS - 1 - t) : t;

        if (t > 0) {
            if (tid == 0) {
                while (*vgen < base + (unsigned)t) { }   // tight spin
                __threadfence();
            }
            __syncthreads();

            const uint4* src = (const uint4*)g_hfrag[(t - 1) & 1][dir];
            uint4* dst = (uint4*)Bsm;
#pragma unroll
            for (int i = 0; i < 8; i++)
                dst[tid + i * 512] = __ldcg(src + tid + i * 512);
            __syncthreads();

            float d0a[4] = {0.f,0.f,0.f,0.f}, d0b[4] = {0.f,0.f,0.f,0.f};
            float d1a[4] = {0.f,0.f,0.f,0.f}, d1b[4] = {0.f,0.f,0.f,0.f};
            uint4 rah[4];
#pragma unroll
            for (int i = 0; i < 4; i++)
                rah[i] = __ldg(Aph + i * 128);

            const uint32_t* Bw = Bsm + (((kbase * 4 + ntbase) * 32 + lid) << 1);
#pragma unroll 4
            for (int ks = 0; ks < 32; ks++) {
                int s = ks & 3;
                uint4 ah = rah[s];
                if (ks < 28) rah[s] = __ldg(Aph + (ks + 4) * 128);
                const uint32_t* bp = Bw + ks * 256;
                uint2 b0 = *(const uint2*)bp;
                uint2 b1 = *(const uint2*)(bp + 64);
                if (ks & 1) {
                    MMA_F16(d0b, ah, b0);
                    MMA_F16(d1b, ah, b1);
                } else {
                    MMA_F16(d0a, ah, b0);
                    MMA_F16(d1a, ah, b1);
                }
            }
            float d0[4], d1[4];
#pragma unroll
            for (int i = 0; i < 4; i++) {
                d0[i] = d0a[i] + d0b[i];
                d1[i] = d1a[i] + d1b[i];
            }
            float* ps = psum + ksplit * (64 * 33);
            int row0 = mtile * 16 + (lid >> 2);
            int n0 = ntbase * 8 + (lid & 3) * 2;
            ps[row0 * 33 + n0]           = d0[0];
            ps[row0 * 33 + n0 + 1]       = d0[1];
            ps[(row0 + 8) * 33 + n0]     = d0[2];
            ps[(row0 + 8) * 33 + n0 + 1] = d0[3];
            ps[row0 * 33 + n0 + 8]           = d1[0];
            ps[row0 * 33 + n0 + 9]           = d1[1];
            ps[(row0 + 8) * 33 + n0 + 8]     = d1[2];
            ps[(row0 + 8) * 33 + n0 + 9]     = d1[3];
            __syncthreads();
        }

        float gi = pg0, gf = pg1, gg = pg2, go = pg3;
        if (t > 0) {
            gi += psum[(0 * 16 + cj) * 33 + cb] + psum[64 * 33 + (0 * 16 + cj) * 33 + cb];
            gf += psum[(1 * 16 + cj) * 33 + cb] + psum[64 * 33 + (1 * 16 + cj) * 33 + cb];
            gg += psum[(2 * 16 + cj) * 33 + cb] + psum[64 * 33 + (2 * 16 + cj) * 33 + cb];
            go += psum[(3 * 16 + cj) * 33 + cb] + psum[64 * 33 + (3 * 16 + cj) * 33 + cb];
        }
        float i_ = 1.f / (1.f + expf(-gi));
        float f_ = 1.f / (1.f + expf(-gf));
        creg = f_ * creg + i_ * tanhf(gg);
        float hv = (1.f / (1.f + expf(-go))) * tanhf(creg);
        __half hvh = __float2half_rn(hv);

        hstage[hloc] = hvh;
        __syncthreads();
        if (tid < 64) {
            uint4 v = ((const uint4*)hstage)[tid];
            *(((uint4*)(g_hfrag[t & 1][dir] + my_kstep * 256)) + tid) = v;
        }
        __threadfence();
        __syncthreads();

        if (tid == 0) {
            unsigned rank = atomicAdd(&g_bar_cnt[dir], 1);
            if (rank == DBAR - 1) {
                atomicExch(&g_bar_cnt[dir], 0);
                __threadfence();
                atomicExch(&g_bar_gen[dir], base + (unsigned)t + 1);
            }
        }

        if (Xfout) {
            int m = sdir * BB + cb;
            int rowblk = m >> 6, r = m & 63;
            int mt = r >> 4, mrow = r & 15;
            int lane2 = (mrow & 7) * 4 + ((xkin >> 1) & 3);
            int reg = ((mrow >> 3) & 1) + ((xkin >> 3) << 1);
            size_t e = (((((size_t)rowblk * 128 + xkstep) * 4 + mt) * 32 + lane2) * 4
                        + reg) * 2 + (xkin & 1);
            Xfout[e] = hvh;
        } else {
            Xout[(size_t)(sdir * BB + cb) * 2048 + dir * HH + j0 + cj] = hv;
        }
        if (t + 1 < SS) {
            const int sdn = dir ? (SS - 2 - t) : (t + 1);
            const __half* pp = preD + (size_t)sdn * BB * G4 + (size_t)cb * G4 + j0 + cj;
            pg0 = __half2float(__ldcg(pp));
            pg1 = __half2float(__ldcg(pp + 1024));
            pg2 = __half2float(__ldcg(pp + 2048));
            pg3 = __half2float(__ldcg(pp + 3072));
        }
    }
}

// ---------------------------------------------------------------------------
// BN + ReLU + lin2 -> emissions
// ---------------------------------------------------------------------------
__global__ void bn_lin2(const float* __restrict__ X, const float* __restrict__ gamma,
                        const float* __restrict__ beta, const float* __restrict__ w2,
                        const float* __restrict__ b2, float* __restrict__ emis) {
    int m = blockIdx.x;
    int s = m / BB, b = m % BB;
    int tid = threadIdx.x;
    const float inv = rsqrtf(1.f + 1e-5f);
    float acc[NT];
#pragma unroll
    for (int j = 0; j < NT; j++) acc[j] = 0.f;
    for (int k = tid; k < 2048; k += 128) {
        float hv = X[(size_t)m * 2048 + k];
        hv = fmaxf(gamma[k] * inv * hv + beta[k], 0.f);
#pragma unroll
        for (int j = 0; j < NT; j++) acc[j] += hv * w2[j * 2048 + k];
    }
    __shared__ float red[NT][128];
#pragma unroll
    for (int j = 0; j < NT; j++) red[j][tid] = acc[j];
    __syncthreads();
    for (int off = 64; off > 0; off >>= 1) {
        if (tid < off) {
#pragma unroll
            for (int j = 0; j < NT; j++) red[j][tid] += red[j][tid + off];
        }
        __syncthreads();
    }
    if (tid < NT) emis[(size_t)(b * SS + s) * NT + tid] = red[tid][0] + b2[tid];
}

// ---------------------------------------------------------------------------
// CRF log-likelihood -> scalar
// ---------------------------------------------------------------------------
__global__ void crf_kernel(const float* __restrict__ emis, const int* __restrict__ y,
                           const unsigned char* __restrict__ maskb,
                           const float* __restrict__ start, const float* __restrict__ end_,
                           const float* __restrict__ trans, float* __restrict__ out) {
    __shared__ float alpha[BB][12];
    __shared__ float tmp[BB][12];
    __shared__ float tr[NT * NT];
    __shared__ float numv[BB];
    __shared__ float denv[BB];
    __shared__ int mask_mode;

    int tid = threadIdx.x;
    if (tid == 0) {
        int mm = 1;
        for (int i = 0; i < 16; i++) {
            if (maskb[4 * i + 1] | maskb[4 * i + 2] | maskb[4 * i + 3]) { mm = 0; break; }
        }
        mask_mode = mm;
    }
    if (tid < NT * NT) tr[tid] = trans[tid];
    __syncthreads();

    int b = tid / NT;
    int j = tid % NT;
    const int mm = mask_mode;
    const int* mi = (const int*)maskb;

    alpha[b][j] = start[j] + emis[(size_t)(b * SS) * NT + j];
    __syncthreads();

    for (int t = 1; t < SS; t++) {
        float mx = -1e30f;
#pragma unroll
        for (int i = 0; i < NT; i++) {
            float v = alpha[b][i] + tr[i * NT + j];
            mx = fmaxf(mx, v);
        }
        float ssum = 0.f;
#pragma unroll
        for (int i = 0; i < NT; i++)
            ssum += expf(alpha[b][i] + tr[i * NT + j] - mx);
        float nxt = mx + logf(ssum) + emis[(size_t)(b * SS + t) * NT + j];
        bool mk = mm ? (mi[b * SS + t] != 0) : (maskb[b * SS + t] != 0);
        __syncthreads();
        if (mk) alpha[b][j] = nxt;
        __syncthreads();
    }

    tmp[b][j] = alpha[b][j] + end_[j];
    __syncthreads();
    if (j == 0) {
        float mx = tmp[b][0];
#pragma unroll
        for (int i = 1; i < NT; i++) mx = fmaxf(mx, tmp[b][i]);
        float ssum = 0.f;
#pragma unroll
        for (int i = 0; i < NT; i++) ssum += expf(tmp[b][i] - mx);
        denv[b] = mx + logf(ssum);

        const int* yb = y + b * SS;
        float num = start[yb[0]] + emis[(size_t)(b * SS) * NT + yb[0]];
        int len = (mm ? (mi[b * SS] != 0) : (maskb[b * SS] != 0)) ? 1 : 0;
        for (int t = 1; t < SS; t++) {
            bool mk = mm ? (mi[b * SS + t] != 0) : (maskb[b * SS + t] != 0);
            if (mk) {
                num += tr[yb[t - 1] * NT + yb[t]] + emis[(size_t)(b * SS + t) * NT + yb[t]];
                len++;
            }
        }
        int last = yb[(len > 0 ? len : 1) - 1];
        num += end_[last];
        numv[b] = num;
    }
    __syncthreads();
    if (tid == 0) {
        float acc = 0.f;
        for (int bb2 = 0; bb2 < BB; bb2++) acc += numv[bb2] - denv[bb2];
        out[0] = acc;
    }
}

// ---------------------------------------------------------------------------
// Host launcher
// ---------------------------------------------------------------------------
extern "C" void kernel_launch(void* const* d_in, const int* in_sizes, int n_in,
                              void* d_out, int out_size) {
    const int*   x       = (const int*)d_in[0];
    const int*   y       = (const int*)d_in[1];
    const unsigned char* mask = (const unsigned char*)d_in[2];
    const float* emb     = (const float*)d_in[3];
    const float* lin1_w  = (const float*)d_in[4];
    const float* lin1_b  = (const float*)d_in[5];
    const float* wih[4]  = {(const float*)d_in[6],  (const float*)d_in[9],
                            (const float*)d_in[12], (const float*)d_in[15]};
    const float* whh[4]  = {(const float*)d_in[7],  (const float*)d_in[10],
                            (const float*)d_in[13], (const float*)d_in[16]};
    const float* bias[4] = {(const float*)d_in[8],  (const float*)d_in[11],
                            (const float*)d_in[14], (const float*)d_in[17]};
    const float* bn_gamma = (const float*)d_in[18];
    const float* bn_beta  = (const float*)d_in[19];
    const float* lin2_w   = (const float*)d_in[20];
    const float* lin2_b   = (const float*)d_in[21];
    const float* crf_start = (const float*)d_in[22];
    const float* crf_end   = (const float*)d_in[23];
    const float* crf_trans = (const float*)d_in[24];

    float *X1, *emis;
    __half *pre;
    uint4 *Ahi, *Xf;
    uint2 *Wf, *WfL1;
    cudaGetSymbolAddress((void**)&X1, g_X1);
    cudaGetSymbolAddress((void**)&pre, g_pre);
    cudaGetSymbolAddress((void**)&emis, g_emis);
    cudaGetSymbolAddress((void**)&Ahi, g_Ahi);
    cudaGetSymbolAddress((void**)&Xf, g_Xf);
    cudaGetSymbolAddress((void**)&Wf, g_Wf);
    cudaGetSymbolAddress((void**)&WfL1, g_WfL1);

    static bool attr_set = false;
    if (!attr_set) {
        cudaFuncSetAttribute(lstm_mma, cudaFuncAttributeMaxDynamicSharedMemorySize,
                             LSTM_SMEM);
        attr_set = true;
    }

    const size_t XF_STRIDE = (size_t)64 * 128 * 4 * 32;   // uint4 per buffer

    // lin1 path: gather+convert E into Xf[1] (scratch), W1 frags, HMMA -> Xf[0]
    convE_kernel<<<(4096 * 304 + 255) / 256, 256>>>(x, emb,
                                                    (__half*)(Xf + XF_STRIDE));
    convW1_kernel<<<(512 * 304 + 255) / 256, 256>>>(lin1_w, (__half*)WfL1);
    hgemm_lin1<<<dim3(2, 32), 512>>>(Xf + XF_STRIDE, WfL1, lin1_b, (__half*)Xf);

    const int Kin[4] = {512, 2048, 2048, 2048};

    for (int l = 0; l < 4; l++) {
        const int K = Kin[l];
        const int KS = K / 16;
        uint4* XfIn  = Xf + (size_t)(l & 1) * XF_STRIDE;
        __half* XfOut = (l < 3) ? (__half*)(Xf + (size_t)((l + 1) & 1) * XF_STRIDE)
                                : (__half*)0;
        convw_kernel<<<(128 * 64 * 512) / 256, 256>>>(whh[l], (uint32_t*)Ahi);
        convwih_kernel<<<(8192 * (K / 2) + 255) / 256, 256>>>(
            wih[l], (uint32_t*)Wf, K, KS);
        hgemm_pre<<<dim3(32, 32), 512>>>(XfIn, Wf, bias[l], pre, KS);
        lstm_mma<<<LBLK, 512, LSTM_SMEM>>>(Ahi, pre, X1, XfOut);
    }

    bn_lin2<<<4096, 128>>>(X1, bn_gamma, bn_beta, lin2_w, lin2_b, emis);
    crf_kernel<<<1, BB * NT>>>(emis, y, mask, crf_start, crf_end, crf_trans,
                               (float*)d_out);
}

// round 17
// speedup vs baseline: 1.2557x; 1.2557x over previous
#include <cuda_runtime.h>
#include <cuda_fp16.h>
#include <cuda_bf16.h>
#include <math.h>
#include <stdint.h>

// ---------------------------------------------------------------------------
// Problem constants
// ---------------------------------------------------------------------------
#define BB 32      // batch
#define SS 128     // seq len
#define DD 300     // emb dim
#define HH 1024    // hidden
#define G4 4096    // 4*H
#define NT 9       // tags
#define LBLK 128   // persistent LSTM CTAs (single wave, <148 SMs)
#define DBAR 64    // per-direction barrier arrivals

// lstm dynamic smem: Bsm u32[16384] (64KB) + psum float[2*64*33] + hstage 1KB
#define LSTM_SMEM (65536 + 2 * 64 * 33 * 4 + 1024)

// ---------------------------------------------------------------------------
// Scratch (static device allocations - allowed)
// ---------------------------------------------------------------------------
__device__ float g_X1[4096 * 2048];             // fp32 layer-3 output for bn_lin2
__device__ __half g_pre[2ull * 4096 * 4096];    // fp16 input projections
__device__ float g_emis[BB * SS * NT];
// Whh fp16, A-fragment order: [cta 128][kstep 64][mtile 4][lane 32][4 u32]
__device__ uint4 g_Ahi[128 * 8192];
// h as fp16 B-fragments, parity double-buffered: [parity][dir][16384 u32]
__device__ uint32_t g_hfrag[2][2][16384];
// input-projection A-fragments, ping-pong
__device__ uint4 g_Xf[2][64 * 128 * 4 * 32];
// Wih B-fragments (reused per layer)
__device__ uint2 g_Wf[256 * 128 * 4 * 32];
// lin1 weight B-fragments (N=512, KS=19)
__device__ uint2 g_WfL1[16 * 19 * 4 * 32];

__device__ unsigned g_bar_cnt[2];
__device__ unsigned g_bar_gen[2];

// mma.sync m16n8k16 fp16 -> f32 (baseline PTX, compiles for plain sm_103)
#define MMA_F16(d, a, b) \
    asm volatile("mma.sync.aligned.m16n8k16.row.col.f32.f16.f16.f32 " \
        "{%0,%1,%2,%3}, {%4,%5,%6,%7}, {%8,%9}, {%0,%1,%2,%3};" \
        : "+f"((d)[0]), "+f"((d)[1]), "+f"((d)[2]), "+f"((d)[3]) \
        : "r"((a).x), "r"((a).y), "r"((a).z), "r"((a).w), \
          "r"((b).x), "r"((b).y))

__device__ __forceinline__ uint32_t pack_h2(float a, float b) {
    return (uint32_t)__half_as_ushort(__float2half_rn(a)) |
           ((uint32_t)__half_as_ushort(__float2half_rn(b)) << 16);
}

// ---------------------------------------------------------------------------
// Fused weight conversion: Whh -> A-fragments AND Wih -> B-fragments,
// one u32 (k-pair) per thread, index-split single launch.
//   [0, NW)            : convw  (NW = 128*64*512)
//   [NW, NW + 8192*K/2): convwih
// ---------------------------------------------------------------------------
#define NW (128 * 64 * 512)
__global__ void conv_weights(const float* __restrict__ whh,
                             const float* __restrict__ wih,
                             uint32_t* __restrict__ Ahi,
                             uint32_t* __restrict__ Wf, int K, int KS) {
    int i = blockIdx.x * blockDim.x + threadIdx.x;
    if (i < NW) {
        int c = i >> 15;
        int r = (i >> 9) & 63;
        int kp = i & 511;
        int kstep = kp >> 3, p = kp & 7;
        int k0 = kstep * 16 + p * 2;
        int dir = c >> 6, j0 = (c & 63) * 16;
        int gate = r >> 4, jj = r & 15;
        int grow = gate * 1024 + j0 + jj;
        const float* wp = whh + (size_t)dir * G4 * HH + (size_t)grow * HH + k0;
        float w0 = wp[0], w1 = wp[1];
        int lane = (jj & 7) * 4 + (p & 3);
        int reg = ((jj >> 3) & 1) + ((p >> 2) << 1);
        size_t idx = (size_t)c * 32768 + kstep * 512 + gate * 128 + lane * 4 + reg;
        Ahi[idx] = pack_h2(w0, w1);
        return;
    }
    i -= NW;
    int KH = K >> 1;
    if (i >= 8192 * KH) return;
    int n = i / KH, kp = i % KH;
    int kstep = kp >> 3, p = kp & 7;
    int k0 = kstep * 16 + p * 2;
    const float* wp = wih + (size_t)n * K + k0;
    float w0 = wp[0], w1 = wp[1];
    int nblk = n >> 5, nr = n & 31;
    int nt = nr >> 3, ncol = nr & 7;
    int lane = ncol * 4 + (p & 3);
    int reg = p >> 2;
    size_t idx = ((((size_t)nblk * KS + kstep) * 4 + nt) * 32 + lane) * 2 + reg;
    Wf[idx] = pack_h2(w0, w1);
}

// ---------------------------------------------------------------------------
// Embedding gather -> fp16 A-fragments (K=304, KS=19, zero pad 300..303)
// ---------------------------------------------------------------------------
__global__ void convE_kernel(const int* __restrict__ x, const float* __restrict__ emb,
                             __half* __restrict__ Ef) {
    int i = blockIdx.x * blockDim.x + threadIdx.x;   // 4096*304
    if (i >= 4096 * 304) return;
    int m = i / 304, k = i % 304;
    int s = m / BB, b = m % BB;
    int tok = x[b * SS + s];
    float v = (k < DD) ? emb[(size_t)tok * DD + k] : 0.f;
    int rowblk = m >> 6, r = m & 63;
    int mt = r >> 4, mrow = r & 15;
    int kstep = k >> 4, kin = k & 15;
    int lane = (mrow & 7) * 4 + ((kin >> 1) & 3);
    int reg = ((mrow >> 3) & 1) + ((kin >> 3) << 1);
    size_t e = (((((size_t)rowblk * 19 + kstep) * 4 + mt) * 32 + lane) * 4 + reg) * 2
               + (kin & 1);
    Ef[e] = __float2half_rn(v);
}

// lin1 weight (512 x 300) -> B-fragments (N=512, KS=19, zero pad)
__global__ void convW1_kernel(const float* __restrict__ W, __half* __restrict__ Wf) {
    int i = blockIdx.x * blockDim.x + threadIdx.x;   // 512*304
    if (i >= 512 * 304) return;
    int n = i / 304, k = i % 304;
    float v = (k < DD) ? W[(size_t)n * DD + k] : 0.f;
    int nblk = n >> 5, nr = n & 31;
    int nt = nr >> 3, ncol = nr & 7;
    int kstep = k >> 4, kin = k & 15;
    int lane = ncol * 4 + ((kin & 7) >> 1);
    int reg = kin >> 3;
    size_t e = (((((size_t)nblk * 19 + kstep) * 4 + nt) * 32 + lane) * 2 + reg) * 2
               + (kin & 1);
    Wf[e] = __float2half_rn(v);
}

// ---------------------------------------------------------------------------
// HMMA lin1: X0frag[m][n] = E[m] . W1[n] + b1[n], written directly as
// fp16 A-fragments (KS=32) for layer-0 hgemm. Grid (2, 32), 512 threads.
// (depth-1 prefetch, R15-proven register footprint)
// ---------------------------------------------------------------------------
__global__ void __launch_bounds__(512, 1)
hgemm_lin1(const uint4* __restrict__ Ef, const uint2* __restrict__ Wf,
           const float* __restrict__ bias, __half* __restrict__ Xf0) {
    const int tid = threadIdx.x;
    const int wid = tid >> 5, lane = tid & 31;
    const int rowblk = blockIdx.y * 2 + (wid >> 3);
    const int nblk = blockIdx.x * 8 + (wid & 7);

    const uint4* Ab = Ef + (size_t)rowblk * 19 * 128 + lane;
    const uint2* Bb = Wf + (size_t)nblk * 19 * 128 + lane;

    float d[4][4][4];
#pragma unroll
    for (int mt = 0; mt < 4; mt++)
#pragma unroll
        for (int nt = 0; nt < 4; nt++)
#pragma unroll
            for (int q = 0; q < 4; q++) d[mt][nt][q] = 0.f;

    uint4 a[4];
    uint2 b[4];
#pragma unroll
    for (int i = 0; i < 4; i++) {
        a[i] = __ldg(Ab + i * 32);
        b[i] = __ldg(Bb + i * 32);
    }
    for (int ks = 0; ks < 19; ks++) {
        uint4 ca[4];
        uint2 cb[4];
#pragma unroll
        for (int i = 0; i < 4; i++) { ca[i] = a[i]; cb[i] = b[i]; }
        if (ks + 1 < 19) {
            const uint4* An = Ab + (size_t)(ks + 1) * 128;
            const uint2* Bn = Bb + (size_t)(ks + 1) * 128;
#pragma unroll
            for (int i = 0; i < 4; i++) {
                a[i] = __ldg(An + i * 32);
                b[i] = __ldg(Bn + i * 32);
            }
        }
#pragma unroll
        for (int mt = 0; mt < 4; mt++)
#pragma unroll
            for (int nt = 0; nt < 4; nt++)
                MMA_F16(d[mt][nt], ca[mt], cb[nt]);
    }

    // epilogue: bias + write fp16 A-fragments (KS=32) for layer-0 hgemm
#pragma unroll
    for (int mt = 0; mt < 4; mt++) {
#pragma unroll
        for (int nt = 0; nt < 4; nt++) {
#pragma unroll
            for (int q = 0; q < 4; q++) {
                int n = nblk * 32 + nt * 8 + (lane & 3) * 2 + (q & 1);
                int mm = rowblk * 64 + mt * 16 + (lane >> 2) + ((q >> 1) << 3);
                float val = d[mt][nt][q] + __ldg(bias + n);
                int kstep = n >> 4, kin = n & 15;
                int rb = mm >> 6, r = mm & 63;
                int mtA = r >> 4, mr = r & 15;
                int lane2 = (mr & 7) * 4 + ((kin >> 1) & 3);
                int reg = ((mr >> 3) & 1) + ((kin >> 3) << 1);
                size_t e = (((((size_t)rb * 32 + kstep) * 4 + mtA) * 32 + lane2) * 4
                            + reg) * 2 + (kin & 1);
                Xf0[e] = __float2half_rn(val);
            }
        }
    }
}

// ---------------------------------------------------------------------------
// HMMA input-projection GEMM: pre[dir][m][col] = X[m] . Wih[n] + bias[n]
// Grid (32, 32), 512 threads; fp16 output; depth-1 prefetch (R15-proven).
// ---------------------------------------------------------------------------
__global__ void __launch_bounds__(512, 1)
hgemm_pre(const uint4* __restrict__ Xf, const uint2* __restrict__ Wf,
          const float* __restrict__ bias, __half* __restrict__ pre, int KS) {
    const int tid = threadIdx.x;
    const int wid = tid >> 5, lane = tid & 31;
    const int rowblk = blockIdx.y * 2 + (wid >> 3);
    const int nblk = blockIdx.x * 8 + (wid & 7);

    const uint4* Ab = Xf + (size_t)rowblk * KS * 128 + lane;
    const uint2* Bb = Wf + (size_t)nblk * KS * 128 + lane;

    float d[4][4][4];
#pragma unroll
    for (int mt = 0; mt < 4; mt++)
#pragma unroll
        for (int nt = 0; nt < 4; nt++)
#pragma unroll
            for (int q = 0; q < 4; q++) d[mt][nt][q] = 0.f;

    uint4 a[4];
    uint2 b[4];
#pragma unroll
    for (int i = 0; i < 4; i++) {
        a[i] = __ldg(Ab + i * 32);
        b[i] = __ldg(Bb + i * 32);
    }

    for (int ks = 0; ks < KS; ks++) {
        uint4 ca[4];
        uint2 cb[4];
#pragma unroll
        for (int i = 0; i < 4; i++) { ca[i] = a[i]; cb[i] = b[i]; }
        if (ks + 1 < KS) {
            const uint4* An = Ab + (size_t)(ks + 1) * 128;
            const uint2* Bn = Bb + (size_t)(ks + 1) * 128;
#pragma unroll
            for (int i = 0; i < 4; i++) {
                a[i] = __ldg(An + i * 32);
                b[i] = __ldg(Bn + i * 32);
            }
        }
#pragma unroll
        for (int mt = 0; mt < 4; mt++)
#pragma unroll
            for (int nt = 0; nt < 4; nt++)
                MMA_F16(d[mt][nt], ca[mt], cb[nt]);
    }

#pragma unroll
    for (int mt = 0; mt < 4; mt++) {
        int m = rowblk * 64 + mt * 16 + (lane >> 2);
#pragma unroll
        for (int nt = 0; nt < 4; nt++) {
            int nn = nblk * 32 + nt * 8 + (lane & 3) * 2;
            int dir = nn >> 12;
            int col = nn & 4095;
            float bs0 = __ldg(bias + nn);
            float bs1 = __ldg(bias + nn + 1);
            __half2* outp = (__half2*)(pre + (size_t)dir * 4096 * 4096
                                       + (size_t)m * 4096 + col);
            *outp = __floats2half2_rn(d[mt][nt][0] + bs0, d[mt][nt][1] + bs1);
            *(outp + (size_t)8 * 2048) =
                __floats2half2_rn(d[mt][nt][2] + bs0, d[mt][nt][3] + bs1);
        }
    }
}

// ---------------------------------------------------------------------------
// Persistent HMMA BiLSTM layer. 128 CTAs x 512 threads. fp16 pre.
// Split arrive/wait barrier (nanosleep poll, R15-proven); coalesced publish.
// ---------------------------------------------------------------------------
__global__ void __launch_bounds__(512, 1)
lstm_mma(const uint4* __restrict__ Ahi, const __half* __restrict__ pre,
         float* __restrict__ Xout, __half* __restrict__ Xfout) {
    extern __shared__ __align__(16) uint32_t smd[];
    uint32_t* Bsm = smd;                           // u32[16384] = 64 KB
    float* psum = (float*)(smd + 16384);           // [ksplit][64 rows][33]
    __half* hstage = (__half*)(smd + 16384 + 2 * 64 * 33);  // 512 halves

    const int tid = threadIdx.x;
    const int wid = tid >> 5;
    const int lid = tid & 31;
    const int cta = blockIdx.x;
    const int dir = cta >> 6;
    const int my_kstep = cta & 63;
    const int j0 = my_kstep * 16;

    const int ksplit = wid >> 3;
    const int mtile  = (wid >> 1) & 3;
    const int ntbase = (wid & 1) * 2;
    const int kbase  = ksplit * 32;

    const uint4* Aph = Ahi + (size_t)cta * 8192 + (size_t)kbase * 128 + mtile * 32 + lid;
    const __half* preD = pre + (size_t)dir * 4096 * 4096;

    const int cb = tid >> 4;
    const int cj = tid & 15;
    float creg = 0.f;

    const int kx = dir * HH + j0 + cj;
    const int xkstep = kx >> 4, xkin = kx & 15;

    const int hloc = (((cb >> 3) * 32 + (cb & 7) * 4 + ((cj & 7) >> 1)) * 2
                      + (cj >> 3)) * 2 + (cj & 1);

    volatile unsigned* vgen = &g_bar_gen[dir];
    const unsigned base = *vgen;

    float pg0, pg1, pg2, pg3;
    {
        const int sd0 = dir ? (SS - 1) : 0;
        const __half* pp = preD + (size_t)sd0 * BB * G4 + (size_t)cb * G4 + j0 + cj;
        pg0 = __half2float(__ldcg(pp));
        pg1 = __half2float(__ldcg(pp + 1024));
        pg2 = __half2float(__ldcg(pp + 2048));
        pg3 = __half2float(__ldcg(pp + 3072));
    }

    for (int t = 0; t < SS; t++) {
        const int sdir = dir ? (SS - 1 - t) : t;

        if (t > 0) {
            if (tid == 0) {
                while (*vgen < base + (unsigned)t) { __nanosleep(32); }
                __threadfence();
            }
            __syncthreads();

            const uint4* src = (const uint4*)g_hfrag[(t - 1) & 1][dir];
            uint4* dst = (uint4*)Bsm;
#pragma unroll
            for (int i = 0; i < 8; i++)
                dst[tid + i * 512] = __ldcg(src + tid + i * 512);
            __syncthreads();

            float d0a[4] = {0.f,0.f,0.f,0.f}, d0b[4] = {0.f,0.f,0.f,0.f};
            float d1a[4] = {0.f,0.f,0.f,0.f}, d1b[4] = {0.f,0.f,0.f,0.f};
            uint4 rah[4];
#pragma unroll
            for (int i = 0; i < 4; i++)
                rah[i] = __ldg(Aph + i * 128);

            const uint32_t* Bw = Bsm + (((kbase * 4 + ntbase) * 32 + lid) << 1);
#pragma unroll 4
            for (int ks = 0; ks < 32; ks++) {
                int s = ks & 3;
                uint4 ah = rah[s];
                if (ks < 28) rah[s] = __ldg(Aph + (ks + 4) * 128);
                const uint32_t* bp = Bw + ks * 256;
                uint2 b0 = *(const uint2*)bp;
                uint2 b1 = *(const uint2*)(bp + 64);
                if (ks & 1) {
                    MMA_F16(d0b, ah, b0);
                    MMA_F16(d1b, ah, b1);
                } else {
                    MMA_F16(d0a, ah, b0);
                    MMA_F16(d1a, ah, b1);
                }
            }
            float d0[4], d1[4];
#pragma unroll
            for (int i = 0; i < 4; i++) {
                d0[i] = d0a[i] + d0b[i];
                d1[i] = d1a[i] + d1b[i];
            }
            float* ps = psum + ksplit * (64 * 33);
            int row0 = mtile * 16 + (lid >> 2);
            int n0 = ntbase * 8 + (lid & 3) * 2;
            ps[row0 * 33 + n0]           = d0[0];
            ps[row0 * 33 + n0 + 1]       = d0[1];
            ps[(row0 + 8) * 33 + n0]     = d0[2];
            ps[(row0 + 8) * 33 + n0 + 1] = d0[3];
            ps[row0 * 33 + n0 + 8]           = d1[0];
            ps[row0 * 33 + n0 + 9]           = d1[1];
            ps[(row0 + 8) * 33 + n0 + 8]     = d1[2];
            ps[(row0 + 8) * 33 + n0 + 9]     = d1[3];
            __syncthreads();
        }

        float gi = pg0, gf = pg1, gg = pg2, go = pg3;
        if (t > 0) {
            gi += psum[(0 * 16 + cj) * 33 + cb] + psum[64 * 33 + (0 * 16 + cj) * 33 + cb];
            gf += psum[(1 * 16 + cj) * 33 + cb] + psum[64 * 33 + (1 * 16 + cj) * 33 + cb];
            gg += psum[(2 * 16 + cj) * 33 + cb] + psum[64 * 33 + (2 * 16 + cj) * 33 + cb];
            go += psum[(3 * 16 + cj) * 33 + cb] + psum[64 * 33 + (3 * 16 + cj) * 33 + cb];
        }
        float i_ = 1.f / (1.f + expf(-gi));
        float f_ = 1.f / (1.f + expf(-gf));
        creg = f_ * creg + i_ * tanhf(gg);
        float hv = (1.f / (1.f + expf(-go))) * tanhf(creg);
        __half hvh = __float2half_rn(hv);

        hstage[hloc] = hvh;
        __syncthreads();
        if (tid < 64) {
            uint4 v = ((const uint4*)hstage)[tid];
            *(((uint4*)(g_hfrag[t & 1][dir] + my_kstep * 256)) + tid) = v;
        }
        __threadfence();
        __syncthreads();

        if (tid == 0) {
            unsigned rank = atomicAdd(&g_bar_cnt[dir], 1);
            if (rank == DBAR - 1) {
                atomicExch(&g_bar_cnt[dir], 0);
                __threadfence();
                atomicExch(&g_bar_gen[dir], base + (unsigned)t + 1);
            }
        }

        if (Xfout) {
            int m = sdir * BB + cb;
            int rowblk = m >> 6, r = m & 63;
            int mt = r >> 4, mrow = r & 15;
            int lane2 = (mrow & 7) * 4 + ((xkin >> 1) & 3);
            int reg = ((mrow >> 3) & 1) + ((xkin >> 3) << 1);
            size_t e = (((((size_t)rowblk * 128 + xkstep) * 4 + mt) * 32 + lane2) * 4
                        + reg) * 2 + (xkin & 1);
            Xfout[e] = hvh;
        } else {
            Xout[(size_t)(sdir * BB + cb) * 2048 + dir * HH + j0 + cj] = hv;
        }
        if (t + 1 < SS) {
            const int sdn = dir ? (SS - 2 - t) : (t + 1);
            const __half* pp = preD + (size_t)sdn * BB * G4 + (size_t)cb * G4 + j0 + cj;
            pg0 = __half2float(__ldcg(pp));
            pg1 = __half2float(__ldcg(pp + 1024));
            pg2 = __half2float(__ldcg(pp + 2048));
            pg3 = __half2float(__ldcg(pp + 3072));
        }
    }
}

// ---------------------------------------------------------------------------
// BN + ReLU + lin2 -> emissions
// ---------------------------------------------------------------------------
__global__ void bn_lin2(const float* __restrict__ X, const float* __restrict__ gamma,
                        const float* __restrict__ beta, const float* __restrict__ w2,
                        const float* __restrict__ b2, float* __restrict__ emis) {
    int m = blockIdx.x;
    int s = m / BB, b = m % BB;
    int tid = threadIdx.x;
    const float inv = rsqrtf(1.f + 1e-5f);
    float acc[NT];
#pragma unroll
    for (int j = 0; j < NT; j++) acc[j] = 0.f;
    for (int k = tid; k < 2048; k += 128) {
        float hv = X[(size_t)m * 2048 + k];
        hv = fmaxf(gamma[k] * inv * hv + beta[k], 0.f);
#pragma unroll
        for (int j = 0; j < NT; j++) acc[j] += hv * w2[j * 2048 + k];
    }
    __shared__ float red[NT][128];
#pragma unroll
    for (int j = 0; j < NT; j++) red[j][tid] = acc[j];
    __syncthreads();
    for (int off = 64; off > 0; off >>= 1) {
        if (tid < off) {
#pragma unroll
            for (int j = 0; j < NT; j++) red[j][tid] += red[j][tid + off];
        }
        __syncthreads();
    }
    if (tid < NT) emis[(size_t)(b * SS + s) * NT + tid] = red[tid][0] + b2[tid];
}

// ---------------------------------------------------------------------------
// CRF log-likelihood -> scalar
// ---------------------------------------------------------------------------
__global__ void crf_kernel(const float* __restrict__ emis, const int* __restrict__ y,
                           const unsigned char* __restrict__ maskb,
                           const float* __restrict__ start, const float* __restrict__ end_,
                           const float* __restrict__ trans, float* __restrict__ out) {
    __shared__ float alpha[BB][12];
    __shared__ float tmp[BB][12];
    __shared__ float tr[NT * NT];
    __shared__ float numv[BB];
    __shared__ float denv[BB];
    __shared__ int mask_mode;

    int tid = threadIdx.x;
    if (tid == 0) {
        int mm = 1;
        for (int i = 0; i < 16; i++) {
            if (maskb[4 * i + 1] | maskb[4 * i + 2] | maskb[4 * i + 3]) { mm = 0; break; }
        }
        mask_mode = mm;
    }
    if (tid < NT * NT) tr[tid] = trans[tid];
    __syncthreads();

    int b = tid / NT;
    int j = tid % NT;
    const int mm = mask_mode;
    const int* mi = (const int*)maskb;

    alpha[b][j] = start[j] + emis[(size_t)(b * SS) * NT + j];
    __syncthreads();

    for (int t = 1; t < SS; t++) {
        float mx = -1e30f;
#pragma unroll
        for (int i = 0; i < NT; i++) {
            float v = alpha[b][i] + tr[i * NT + j];
            mx = fmaxf(mx, v);
        }
        float ssum = 0.f;
#pragma unroll
        for (int i = 0; i < NT; i++)
            ssum += expf(alpha[b][i] + tr[i * NT + j] - mx);
        float nxt = mx + logf(ssum) + emis[(size_t)(b * SS + t) * NT + j];
        bool mk = mm ? (mi[b * SS + t] != 0) : (maskb[b * SS + t] != 0);
        __syncthreads();
        if (mk) alpha[b][j] = nxt;
        __syncthreads();
    }

    tmp[b][j] = alpha[b][j] + end_[j];
    __syncthreads();
    if (j == 0) {
        float mx = tmp[b][0];
#pragma unroll
        for (int i = 1; i < NT; i++) mx = fmaxf(mx, tmp[b][i]);
        float ssum = 0.f;
#pragma unroll
        for (int i = 0; i < NT; i++) ssum += expf(tmp[b][i] - mx);
        denv[b] = mx + logf(ssum);

        const int* yb = y + b * SS;
        float num = start[yb[0]] + emis[(size_t)(b * SS) * NT + yb[0]];
        int len = (mm ? (mi[b * SS] != 0) : (maskb[b * SS] != 0)) ? 1 : 0;
        for (int t = 1; t < SS; t++) {
            bool mk = mm ? (mi[b * SS + t] != 0) : (maskb[b * SS + t] != 0);
            if (mk) {
                num += tr[yb[t - 1] * NT + yb[t]] + emis[(size_t)(b * SS + t) * NT + yb[t]];
                len++;
            }
        }
        int last = yb[(len > 0 ? len : 1) - 1];
        num += end_[last];
        numv[b] = num;
    }
    __syncthreads();
    if (tid == 0) {
        float acc = 0.f;
        for (int bb2 = 0; bb2 < BB; bb2++) acc += numv[bb2] - denv[bb2];
        out[0] = acc;
    }
}

// ---------------------------------------------------------------------------
// Host launcher
// ---------------------------------------------------------------------------
extern "C" void kernel_launch(void* const* d_in, const int* in_sizes, int n_in,
                              void* d_out, int out_size) {
    const int*   x       = (const int*)d_in[0];
    const int*   y       = (const int*)d_in[1];
    const unsigned char* mask = (const unsigned char*)d_in[2];
    const float* emb     = (const float*)d_in[3];
    const float* lin1_w  = (const float*)d_in[4];
    const float* lin1_b  = (const float*)d_in[5];
    const float* wih[4]  = {(const float*)d_in[6],  (const float*)d_in[9],
                            (const float*)d_in[12], (const float*)d_in[15]};
    const float* whh[4]  = {(const float*)d_in[7],  (const float*)d_in[10],
                            (const float*)d_in[13], (const float*)d_in[16]};
    const float* bias[4] = {(const float*)d_in[8],  (const float*)d_in[11],
                            (const float*)d_in[14], (const float*)d_in[17]};
    const float* bn_gamma = (const float*)d_in[18];
    const float* bn_beta  = (const float*)d_in[19];
    const float* lin2_w   = (const float*)d_in[20];
    const float* lin2_b   = (const float*)d_in[21];
    const float* crf_start = (const float*)d_in[22];
    const float* crf_end   = (const float*)d_in[23];
    const float* crf_trans = (const float*)d_in[24];

    float *X1, *emis;
    __half *pre;
    uint4 *Ahi, *Xf;
    uint2 *Wf, *WfL1;
    cudaGetSymbolAddress((void**)&X1, g_X1);
    cudaGetSymbolAddress((void**)&pre, g_pre);
    cudaGetSymbolAddress((void**)&emis, g_emis);
    cudaGetSymbolAddress((void**)&Ahi, g_Ahi);
    cudaGetSymbolAddress((void**)&Xf, g_Xf);
    cudaGetSymbolAddress((void**)&Wf, g_Wf);
    cudaGetSymbolAddress((void**)&WfL1, g_WfL1);

    static bool attr_set = false;
    if (!attr_set) {
        cudaFuncSetAttribute(lstm_mma, cudaFuncAttributeMaxDynamicSharedMemorySize,
                             LSTM_SMEM);
        attr_set = true;
    }

    const size_t XF_STRIDE = (size_t)64 * 128 * 4 * 32;   // uint4 per buffer

    // lin1 path: gather+convert E into Xf[1] (scratch), W1 frags, HMMA -> Xf[0]
    convE_kernel<<<(4096 * 304 + 255) / 256, 256>>>(x, emb,
                                                    (__half*)(Xf + XF_STRIDE));
    convW1_kernel<<<(512 * 304 + 255) / 256, 256>>>(lin1_w, (__half*)WfL1);
    hgemm_lin1<<<dim3(2, 32), 512>>>(Xf + XF_STRIDE, WfL1, lin1_b, (__half*)Xf);

    const int Kin[4] = {512, 2048, 2048, 2048};

    for (int l = 0; l < 4; l++) {
        const int K = Kin[l];
        const int KS = K / 16;
        uint4* XfIn  = Xf + (size_t)(l & 1) * XF_STRIDE;
        __half* XfOut = (l < 3) ? (__half*)(Xf + (size_t)((l + 1) & 1) * XF_STRIDE)
                                : (__half*)0;
        int total = NW + 8192 * (K / 2);
        conv_weights<<<(total + 255) / 256, 256>>>(
            whh[l], wih[l], (uint32_t*)Ahi, (uint32_t*)Wf, K, KS);
        hgemm_pre<<<dim3(32, 32), 512>>>(XfIn, Wf, bias[l], pre, KS);
        lstm_mma<<<LBLK, 512, LSTM_SMEM>>>(Ahi, pre, X1, XfOut);
    }

    bn_lin2<<<4096, 128>>>(X1, bn_gamma, bn_beta, lin2_w, lin2_b, emis);
    crf_kernel<<<1, BB * NT>>>(emis, y, mask, crf_start, crf_end, crf_trans,
                               (float*)d_out);
}